// round 15
// baseline (speedup 1.0000x reference)
#include <cuda_runtime.h>

// FHN dynamics — persistent CTAs (6/SM, grid=888), 8 elems/thread,
// packed f32x2 recurrence in (v, z=dt*(I-w)) form, clip-free (proven),
// sigmoid gate via single MUFU.TANH: 0.1+0.9*sig(10(|s|-.5)) = 0.55+0.45*tanh(5|s|-2.5).
// Row = 2048 fp32, 16384 rows. 1 barrier per row.

#define ROW_LEN 2048
#define THREADS 256
#define GRID    888          // 6 CTAs/SM x 148 SMs -> one balanced wave
#define HALF    1024

typedef unsigned long long u64;

__device__ __forceinline__ u64 pk2(float lo, float hi) {
    u64 r; asm("mov.b64 %0, {%1, %2};" : "=l"(r) : "f"(lo), "f"(hi)); return r;
}
__device__ __forceinline__ void upk2(u64 x, float& lo, float& hi) {
    asm("mov.b64 {%0, %1}, %2;" : "=f"(lo), "=f"(hi) : "l"(x));
}
__device__ __forceinline__ u64 mul2(u64 a, u64 b) {
    u64 r; asm("mul.rn.f32x2 %0, %1, %2;" : "=l"(r) : "l"(a), "l"(b)); return r;
}
__device__ __forceinline__ u64 fma2(u64 a, u64 b, u64 c) {
    u64 r; asm("fma.rn.f32x2 %0, %1, %2, %3;" : "=l"(r) : "l"(a), "l"(b), "l"(c)); return r;
}
__device__ __forceinline__ float rcp_fast(float x) {
    float r; asm("rcp.approx.f32 %0, %1;" : "=f"(r) : "f"(x)); return r;
}
__device__ __forceinline__ float tanh_fast(float x) {
    float r; asm("tanh.approx.f32 %0, %1;" : "=f"(r) : "f"(x)); return r;
}

__global__ __launch_bounds__(THREADS, 6)
void fhn_kernel(const float* __restrict__ stim,
                const float* __restrict__ p_a,
                const float* __restrict__ p_b,
                const float* __restrict__ p_dt,
                float* __restrict__ out_resp,
                float* __restrict__ out_v,
                int rows, int write_v)
{
    __shared__ float warp_max[2][8];

    const int t    = threadIdx.x;
    const int lane = t & 31;
    const int wid  = t >> 5;

    // ---- scalar params ----
    const float a  = *p_a;
    const float b  = *p_b;
    const float dt = *p_dt;

    const float alpha = dt * (1.0f / 12.5f);
    const float rd    = rcp_fast(1.0f + alpha * b);   // 1/denom

    // Recurrence in (v, z) with z = dt*(I - w):
    //   q  = (1+dt) - (dt/3) v^2
    //   vn = v*q + z
    //   z' = rd*z + m + (-dt*alpha*rd)*vn,   m = dt*(1-rd)*I - dt*alpha*a*rd
    //   z1 = dt*(1-alpha*rd)*I - dt*alpha*a*rd
    const float dtar   = dt * alpha * rd;
    const u64 cNegDt3  = pk2(-dt * (1.0f/3.0f), -dt * (1.0f/3.0f));
    const u64 cOnePdt  = pk2(1.0f + dt, 1.0f + dt);
    const u64 cRd      = pk2(rd, rd);
    const u64 cNegDtAR = pk2(-dtar, -dtar);
    const u64 cZc      = pk2(-dtar * a, -dtar * a);        // -dt*alpha*a*rd
    const u64 cDt1mR   = pk2(dt * (1.0f - rd), dt * (1.0f - rd));
    const u64 cZ1      = pk2(dt - dtar, dt - dtar);        // dt*(1 - alpha*rd)

    // ---- per-thread incremental pointers ----
    const size_t base = (size_t)blockIdx.x * ROW_LEN + (unsigned)t * 4;
    const float* sp = stim     + base;
    float*       rp = out_resp + base;
    float*       vp = out_v    + base;
    const size_t step = (size_t)GRID * ROW_LEN;

    unsigned row = blockIdx.x;
    int par = 0;

    float4 cur0 = __ldcs((const float4*)(sp));
    float4 cur1 = __ldcs((const float4*)(sp + HALF));

    #pragma unroll 1
    while (row < (unsigned)rows) {
        const unsigned nrow = row + GRID;

        // prefetch next row (2 independent LDG.128 in flight across this row)
        float4 nxt0, nxt1;
        if (nrow < (unsigned)rows) {
            nxt0 = __ldcs((const float4*)(sp + step));
            nxt1 = __ldcs((const float4*)(sp + step + HALF));
        }

        // ---- row max|stim|: REDUX -> STS -> bar -> LDS+REDUX ----
        float m = fmaxf(fmaxf(fmaxf(fabsf(cur0.x), fabsf(cur0.y)),
                              fmaxf(fabsf(cur0.z), fabsf(cur0.w))),
                        fmaxf(fmaxf(fabsf(cur1.x), fabsf(cur1.y)),
                              fmaxf(fabsf(cur1.z), fabsf(cur1.w))));
        unsigned mb = __reduce_max_sync(0xffffffffu, __float_as_uint(m));
        if (lane == 0) warp_max[par][wid] = __uint_as_float(mb);
        __syncthreads();
        {
            unsigned p = __float_as_uint(warp_max[par][lane & 7]);
            mb = __reduce_max_sync(0xffffffffu, p);
        }
        const float scale     = fmaxf(__uint_as_float(mb), 1e-6f);
        const float inv_scale = rcp_fast(scale);

        // ---- I = (s/scale) * (0.55 + 0.45*tanh(5|s| - 2.5)) ----
        float sv[8] = { cur0.x, cur0.y, cur0.z, cur0.w,
                        cur1.x, cur1.y, cur1.z, cur1.w };
        float If[8];
        #pragma unroll
        for (int i = 0; i < 8; i++) {
            const float th   = tanh_fast(fmaf(fabsf(sv[i]), 5.0f, -2.5f));
            const float gate = fmaf(0.45f, th, 0.55f);
            If[i] = sv[i] * inv_scale * gate;
        }

        u64 v[4], z[4], zm[4];
        #pragma unroll
        for (int j = 0; j < 4; j++) {
            const u64 Ipk = pk2(If[2*j], If[2*j+1]);
            v[j]  = Ipk;                          // v1 = I
            zm[j] = fma2(Ipk, cDt1mR, cZc);       // m
            z[j]  = fma2(Ipk, cZ1, cZc);          // z1
        }

        // steps 2..8, clip-free (trajectories provably within ±2.6 < 3)
        #pragma unroll
        for (int stp = 2; stp <= 8; stp++) {
            #pragma unroll
            for (int j = 0; j < 4; j++) {
                const u64 v2 = mul2(v[j], v[j]);
                const u64 q  = fma2(v2, cNegDt3, cOnePdt);   // (1+dt)-(dt/3)v^2
                const u64 vn = fma2(v[j], q, z[j]);          // v_next
                if (stp < 8) {
                    const u64 t1 = fma2(z[j], cRd, zm[j]);
                    z[j] = fma2(vn, cNegDtAR, t1);
                }
                v[j] = vn;
            }
        }

        // ---- outputs: response = v*scale, and v (streaming stores) ----
        const u64 cScale = pk2(scale, scale);
        float4 o0, o1;
        upk2(mul2(v[0], cScale), o0.x, o0.y);
        upk2(mul2(v[1], cScale), o0.z, o0.w);
        upk2(mul2(v[2], cScale), o1.x, o1.y);
        upk2(mul2(v[3], cScale), o1.z, o1.w);
        __stcs((float4*)(rp),        o0);
        __stcs((float4*)(rp + HALF), o1);
        if (write_v) {
            float4 w0, w1;
            upk2(v[0], w0.x, w0.y);
            upk2(v[1], w0.z, w0.w);
            upk2(v[2], w1.x, w1.y);
            upk2(v[3], w1.z, w1.w);
            __stcs((float4*)(vp),        w0);
            __stcs((float4*)(vp + HALF), w1);
        }

        cur0 = nxt0; cur1 = nxt1;
        sp += step; rp += step; vp += step;
        row = nrow;
        par ^= 1;
    }
}

extern "C" void kernel_launch(void* const* d_in, const int* in_sizes, int n_in,
                              void* d_out, int out_size)
{
    const float* stim = (const float*)d_in[0];
    const float* p_a  = (const float*)d_in[1];
    const float* p_b  = (const float*)d_in[2];
    const float* p_dt = (const float*)d_in[3];

    const int total = in_sizes[0];          // 33554432
    const int rows  = total / ROW_LEN;      // 16384

    float* out      = (float*)d_out;
    float* out_resp = out;
    float* out_v    = out + (size_t)total;
    const int write_v = (out_size >= 2 * total) ? 1 : 0;

    fhn_kernel<<<GRID, THREADS>>>(stim, p_a, p_b, p_dt, out_resp, out_v,
                                  rows, write_v);
}